// round 2
// baseline (speedup 1.0000x reference)
#include <cuda_runtime.h>
#include <math.h>

// ---------------------------------------------------------------------------
// Fused kernel: every block composes the 5 tiny linear layers (7->5->4->3->2->1)
// into a single 7->1 affine map (done by thread 0 into shared memory; the W/b
// tensors are tiny and L2-resident after the first wave), then streams
// sigmoid(X @ w_eff + b_eff) with 4 rows per thread (7x float4 loads,
// 1x float4 store).
// ---------------------------------------------------------------------------

__device__ __forceinline__ void compose_weff(
    const float* __restrict__ W1, const float* __restrict__ b1,
    const float* __restrict__ W2, const float* __restrict__ b2,
    const float* __restrict__ W3, const float* __restrict__ b3,
    const float* __restrict__ W4, const float* __restrict__ b4,
    const float* __restrict__ W5, const float* __restrict__ b5,
    float* __restrict__ weff /* [8]: 7 weights + bias */)
{
    const int dims[6] = {7, 5, 4, 3, 2, 1};
    const float* Ws[5] = {W1, W2, W3, W4, W5};
    const float* bs[5] = {b1, b2, b3, b4, b5};

    // M = W1 (7x5), then M = M @ Wk
    float M[7 * 5];
    int cols = dims[1];
    for (int i = 0; i < 7; i++)
        for (int j = 0; j < cols; j++)
            M[i * cols + j] = W1[i * cols + j];

    float tmp[7 * 5];
    for (int k = 1; k < 5; k++) {
        int inner = dims[k], nc = dims[k + 1];
        const float* Wk = Ws[k];
        for (int i = 0; i < 7; i++) {
            for (int j = 0; j < nc; j++) {
                float s = 0.f;
                for (int p = 0; p < inner; p++)
                    s += M[i * cols + p] * Wk[p * nc + j];
                tmp[i * nc + j] = s;
            }
        }
        cols = nc;
        for (int i = 0; i < 7 * cols; i++) M[i] = tmp[i];
    }
    // M is now 7x1

    // bias chain: v = b1; v = v @ W_{k+1} + b_{k+1}
    float v[5], vt[5];
    int vn = dims[1];
    for (int j = 0; j < vn; j++) v[j] = bs[0][j];
    for (int k = 1; k < 5; k++) {
        int nc = dims[k + 1];
        const float* Wk = Ws[k];
        for (int j = 0; j < nc; j++) {
            float s = bs[k][j];
            for (int p = 0; p < vn; p++)
                s += v[p] * Wk[p * nc + j];
            vt[j] = s;
        }
        vn = nc;
        for (int j = 0; j < vn; j++) v[j] = vt[j];
    }

    for (int i = 0; i < 7; i++) weff[i] = M[i];
    weff[7] = v[0];
}

__global__ void __launch_bounds__(256)
mlp_fused_kernel(const float* __restrict__ X, float* __restrict__ out, int nrows,
                 const float* __restrict__ W1, const float* __restrict__ b1,
                 const float* __restrict__ W2, const float* __restrict__ b2,
                 const float* __restrict__ W3, const float* __restrict__ b3,
                 const float* __restrict__ W4, const float* __restrict__ b4,
                 const float* __restrict__ W5, const float* __restrict__ b5)
{
    __shared__ float s_weff[8];

    if (threadIdx.x == 0) {
        compose_weff(W1, b1, W2, b2, W3, b3, W4, b4, W5, b5, s_weff);
    }
    __syncthreads();

    const float w0 = s_weff[0], w1 = s_weff[1], w2 = s_weff[2], w3 = s_weff[3];
    const float w4 = s_weff[4], w5 = s_weff[5], w6 = s_weff[6], be = s_weff[7];

    int t = blockIdx.x * blockDim.x + threadIdx.x;
    long long row0 = (long long)t * 4;
    if (row0 >= nrows) return;

    if (row0 + 4 <= nrows) {
        // 28 consecutive floats; base byte offset 112*t -> 16B aligned
        const float4* Xv = reinterpret_cast<const float4*>(X + row0 * 7);
        float4 p0 = Xv[0], p1 = Xv[1], p2 = Xv[2], p3 = Xv[3];
        float4 p4 = Xv[4], p5 = Xv[5], p6 = Xv[6];

        float f[28];
        f[0]=p0.x; f[1]=p0.y; f[2]=p0.z; f[3]=p0.w;
        f[4]=p1.x; f[5]=p1.y; f[6]=p1.z; f[7]=p1.w;
        f[8]=p2.x; f[9]=p2.y; f[10]=p2.z; f[11]=p2.w;
        f[12]=p3.x; f[13]=p3.y; f[14]=p3.z; f[15]=p3.w;
        f[16]=p4.x; f[17]=p4.y; f[18]=p4.z; f[19]=p4.w;
        f[20]=p5.x; f[21]=p5.y; f[22]=p5.z; f[23]=p5.w;
        f[24]=p6.x; f[25]=p6.y; f[26]=p6.z; f[27]=p6.w;

        float r[4];
        #pragma unroll
        for (int r4 = 0; r4 < 4; r4++) {
            const float* x = f + r4 * 7;
            float z = be;
            z = fmaf(x[0], w0, z);
            z = fmaf(x[1], w1, z);
            z = fmaf(x[2], w2, z);
            z = fmaf(x[3], w3, z);
            z = fmaf(x[4], w4, z);
            z = fmaf(x[5], w5, z);
            z = fmaf(x[6], w6, z);
            r[r4] = 1.0f / (1.0f + __expf(-z));
        }

        float4 o;
        o.x = r[0]; o.y = r[1]; o.z = r[2]; o.w = r[3];
        reinterpret_cast<float4*>(out + row0)[0] = o;
    } else {
        for (long long rr = row0; rr < nrows; rr++) {
            const float* x = X + rr * 7;
            float z = be;
            z = fmaf(x[0], w0, z);
            z = fmaf(x[1], w1, z);
            z = fmaf(x[2], w2, z);
            z = fmaf(x[3], w3, z);
            z = fmaf(x[4], w4, z);
            z = fmaf(x[5], w5, z);
            z = fmaf(x[6], w6, z);
            out[rr] = 1.0f / (1.0f + __expf(-z));
        }
    }
}

extern "C" void kernel_launch(void* const* d_in, const int* in_sizes, int n_in,
                              void* d_out, int out_size)
{
    const float* X  = (const float*)d_in[0];
    const float* W1 = (const float*)d_in[1];
    const float* b1 = (const float*)d_in[2];
    const float* W2 = (const float*)d_in[3];
    const float* b2 = (const float*)d_in[4];
    const float* W3 = (const float*)d_in[5];
    const float* b3 = (const float*)d_in[6];
    const float* W4 = (const float*)d_in[7];
    const float* b4 = (const float*)d_in[8];
    const float* W5 = (const float*)d_in[9];
    const float* b5 = (const float*)d_in[10];
    float* out = (float*)d_out;

    int nrows = in_sizes[0] / 7;

    int nthreads = (nrows + 3) / 4;
    int blocks = (nthreads + 255) / 256;
    mlp_fused_kernel<<<blocks, 256>>>(X, out, nrows,
                                      W1, b1, W2, b2, W3, b3, W4, b4, W5, b5);
}

// round 3
// speedup vs baseline: 4.1730x; 4.1730x over previous
#include <cuda_runtime.h>
#include <math.h>

// ---------------------------------------------------------------------------
// Fused kernel. Per-block prologue: thread 0 composes the 5 tiny linears
// (7->5->4->3->2->1) into one 7->1 affine map using fully-unrolled scalar
// code (no arrays -> no local memory; ~90 independent LDGs issued in one
// batch, ~65 FMAs). Then the block streams sigmoid(X @ w_eff + b_eff),
// 4 rows per thread (7x float4 loads, 1x float4 store).
// ---------------------------------------------------------------------------

__global__ void __launch_bounds__(256)
mlp_fused_kernel(const float* __restrict__ X, float* __restrict__ out, int nrows,
                 const float* __restrict__ W1, const float* __restrict__ b1,
                 const float* __restrict__ W2, const float* __restrict__ b2,
                 const float* __restrict__ W3, const float* __restrict__ b3,
                 const float* __restrict__ W4, const float* __restrict__ b4,
                 const float* __restrict__ W5, const float* __restrict__ b5)
{
    __shared__ float s_weff[8];

    if (threadIdx.x == 0) {
        // ---- fully unrolled compose, scalar registers only ----
        // W5: 2x1
        const float c50 = W5[0], c51 = W5[1];

        // w45 = W4(3x2) @ W5 : 3x1
        const float w45_0 = fmaf(W4[0], c50, W4[1] * c51);
        const float w45_1 = fmaf(W4[2], c50, W4[3] * c51);
        const float w45_2 = fmaf(W4[4], c50, W4[5] * c51);

        // w345 = W3(4x3) @ w45 : 4x1
        const float w345_0 = fmaf(W3[0],  w45_0, fmaf(W3[1],  w45_1, W3[2]  * w45_2));
        const float w345_1 = fmaf(W3[3],  w45_0, fmaf(W3[4],  w45_1, W3[5]  * w45_2));
        const float w345_2 = fmaf(W3[6],  w45_0, fmaf(W3[7],  w45_1, W3[8]  * w45_2));
        const float w345_3 = fmaf(W3[9],  w45_0, fmaf(W3[10], w45_1, W3[11] * w45_2));

        // w2345 = W2(5x4) @ w345 : 5x1
        const float w2345_0 = fmaf(W2[0],  w345_0, fmaf(W2[1],  w345_1, fmaf(W2[2],  w345_2, W2[3]  * w345_3)));
        const float w2345_1 = fmaf(W2[4],  w345_0, fmaf(W2[5],  w345_1, fmaf(W2[6],  w345_2, W2[7]  * w345_3)));
        const float w2345_2 = fmaf(W2[8],  w345_0, fmaf(W2[9],  w345_1, fmaf(W2[10], w345_2, W2[11] * w345_3)));
        const float w2345_3 = fmaf(W2[12], w345_0, fmaf(W2[13], w345_1, fmaf(W2[14], w345_2, W2[15] * w345_3)));
        const float w2345_4 = fmaf(W2[16], w345_0, fmaf(W2[17], w345_1, fmaf(W2[18], w345_2, W2[19] * w345_3)));

        // weff = W1(7x5) @ w2345 : 7x1
        #pragma unroll
        for (int i = 0; i < 7; i++) {
            float s = fmaf(W1[i*5 + 0], w2345_0,
                      fmaf(W1[i*5 + 1], w2345_1,
                      fmaf(W1[i*5 + 2], w2345_2,
                      fmaf(W1[i*5 + 3], w2345_3,
                           W1[i*5 + 4] * w2345_4))));
            s_weff[i] = s;
        }

        // bias chain: be = b5 + b4@W5 + b3.w45 + b2.w345 + b1.w2345
        float be = b5[0];
        be = fmaf(b4[0], c50, be);
        be = fmaf(b4[1], c51, be);
        be = fmaf(b3[0], w45_0, be);
        be = fmaf(b3[1], w45_1, be);
        be = fmaf(b3[2], w45_2, be);
        be = fmaf(b2[0], w345_0, be);
        be = fmaf(b2[1], w345_1, be);
        be = fmaf(b2[2], w345_2, be);
        be = fmaf(b2[3], w345_3, be);
        be = fmaf(b1[0], w2345_0, be);
        be = fmaf(b1[1], w2345_1, be);
        be = fmaf(b1[2], w2345_2, be);
        be = fmaf(b1[3], w2345_3, be);
        be = fmaf(b1[4], w2345_4, be);
        s_weff[7] = be;
    }
    __syncthreads();

    const float w0 = s_weff[0], w1 = s_weff[1], w2 = s_weff[2], w3 = s_weff[3];
    const float w4 = s_weff[4], w5 = s_weff[5], w6 = s_weff[6], be = s_weff[7];

    int t = blockIdx.x * blockDim.x + threadIdx.x;
    long long row0 = (long long)t * 4;
    if (row0 >= nrows) return;

    if (row0 + 4 <= nrows) {
        // 28 consecutive floats; base byte offset 112*t -> 16B aligned
        const float4* Xv = reinterpret_cast<const float4*>(X + row0 * 7);
        float4 p0 = Xv[0], p1 = Xv[1], p2 = Xv[2], p3 = Xv[3];
        float4 p4 = Xv[4], p5 = Xv[5], p6 = Xv[6];

        float f[28];
        f[0]=p0.x; f[1]=p0.y; f[2]=p0.z; f[3]=p0.w;
        f[4]=p1.x; f[5]=p1.y; f[6]=p1.z; f[7]=p1.w;
        f[8]=p2.x; f[9]=p2.y; f[10]=p2.z; f[11]=p2.w;
        f[12]=p3.x; f[13]=p3.y; f[14]=p3.z; f[15]=p3.w;
        f[16]=p4.x; f[17]=p4.y; f[18]=p4.z; f[19]=p4.w;
        f[20]=p5.x; f[21]=p5.y; f[22]=p5.z; f[23]=p5.w;
        f[24]=p6.x; f[25]=p6.y; f[26]=p6.z; f[27]=p6.w;

        float r[4];
        #pragma unroll
        for (int r4 = 0; r4 < 4; r4++) {
            const float* x = f + r4 * 7;
            float z = be;
            z = fmaf(x[0], w0, z);
            z = fmaf(x[1], w1, z);
            z = fmaf(x[2], w2, z);
            z = fmaf(x[3], w3, z);
            z = fmaf(x[4], w4, z);
            z = fmaf(x[5], w5, z);
            z = fmaf(x[6], w6, z);
            r[r4] = 1.0f / (1.0f + __expf(-z));
        }

        float4 o;
        o.x = r[0]; o.y = r[1]; o.z = r[2]; o.w = r[3];
        reinterpret_cast<float4*>(out + row0)[0] = o;
    } else {
        for (long long rr = row0; rr < nrows; rr++) {
            const float* x = X + rr * 7;
            float z = be;
            z = fmaf(x[0], w0, z);
            z = fmaf(x[1], w1, z);
            z = fmaf(x[2], w2, z);
            z = fmaf(x[3], w3, z);
            z = fmaf(x[4], w4, z);
            z = fmaf(x[5], w5, z);
            z = fmaf(x[6], w6, z);
            out[rr] = 1.0f / (1.0f + __expf(-z));
        }
    }
}

extern "C" void kernel_launch(void* const* d_in, const int* in_sizes, int n_in,
                              void* d_out, int out_size)
{
    const float* X  = (const float*)d_in[0];
    const float* W1 = (const float*)d_in[1];
    const float* b1 = (const float*)d_in[2];
    const float* W2 = (const float*)d_in[3];
    const float* b2 = (const float*)d_in[4];
    const float* W3 = (const float*)d_in[5];
    const float* b3 = (const float*)d_in[6];
    const float* W4 = (const float*)d_in[7];
    const float* b4 = (const float*)d_in[8];
    const float* W5 = (const float*)d_in[9];
    const float* b5 = (const float*)d_in[10];
    float* out = (float*)d_out;

    int nrows = in_sizes[0] / 7;

    int nthreads = (nrows + 3) / 4;
    int blocks = (nthreads + 255) / 256;
    mlp_fused_kernel<<<blocks, 256>>>(X, out, nrows,
                                      W1, b1, W2, b2, W3, b3, W4, b4, W5, b5);
}

// round 4
// speedup vs baseline: 4.5224x; 1.0837x over previous
#include <cuda_runtime.h>
#include <math.h>

// ---------------------------------------------------------------------------
// Persistent fused kernel.
//  - grid = #SMs * 8 blocks of 256 threads, grid-stride over row-quads.
//  - Per-block prologue (once, all blocks concurrent at t=0): thread 0
//    composes the 5 tiny linears (7->5->4->3->2->1) into one 7->1 affine map
//    using fully-unrolled scalar code (no local memory).
//  - Main loop: each iteration a thread handles 4 rows = 7x float4 streaming
//    loads (__ldcs) + 1x float4 streaming store (__stcs).
// ---------------------------------------------------------------------------

__global__ void __launch_bounds__(256)
mlp_persistent_kernel(const float* __restrict__ X, float* __restrict__ out, int nrows,
                      const float* __restrict__ W1, const float* __restrict__ b1,
                      const float* __restrict__ W2, const float* __restrict__ b2,
                      const float* __restrict__ W3, const float* __restrict__ b3,
                      const float* __restrict__ W4, const float* __restrict__ b4,
                      const float* __restrict__ W5, const float* __restrict__ b5)
{
    __shared__ float s_weff[8];

    if (threadIdx.x == 0) {
        // ---- fully unrolled compose, scalar registers only ----
        const float c50 = W5[0], c51 = W5[1];

        const float w45_0 = fmaf(W4[0], c50, W4[1] * c51);
        const float w45_1 = fmaf(W4[2], c50, W4[3] * c51);
        const float w45_2 = fmaf(W4[4], c50, W4[5] * c51);

        const float w345_0 = fmaf(W3[0],  w45_0, fmaf(W3[1],  w45_1, W3[2]  * w45_2));
        const float w345_1 = fmaf(W3[3],  w45_0, fmaf(W3[4],  w45_1, W3[5]  * w45_2));
        const float w345_2 = fmaf(W3[6],  w45_0, fmaf(W3[7],  w45_1, W3[8]  * w45_2));
        const float w345_3 = fmaf(W3[9],  w45_0, fmaf(W3[10], w45_1, W3[11] * w45_2));

        const float w2345_0 = fmaf(W2[0],  w345_0, fmaf(W2[1],  w345_1, fmaf(W2[2],  w345_2, W2[3]  * w345_3)));
        const float w2345_1 = fmaf(W2[4],  w345_0, fmaf(W2[5],  w345_1, fmaf(W2[6],  w345_2, W2[7]  * w345_3)));
        const float w2345_2 = fmaf(W2[8],  w345_0, fmaf(W2[9],  w345_1, fmaf(W2[10], w345_2, W2[11] * w345_3)));
        const float w2345_3 = fmaf(W2[12], w345_0, fmaf(W2[13], w345_1, fmaf(W2[14], w345_2, W2[15] * w345_3)));
        const float w2345_4 = fmaf(W2[16], w345_0, fmaf(W2[17], w345_1, fmaf(W2[18], w345_2, W2[19] * w345_3)));

        #pragma unroll
        for (int i = 0; i < 7; i++) {
            s_weff[i] = fmaf(W1[i*5 + 0], w2345_0,
                        fmaf(W1[i*5 + 1], w2345_1,
                        fmaf(W1[i*5 + 2], w2345_2,
                        fmaf(W1[i*5 + 3], w2345_3,
                             W1[i*5 + 4] * w2345_4))));
        }

        float be = b5[0];
        be = fmaf(b4[0], c50, be);
        be = fmaf(b4[1], c51, be);
        be = fmaf(b3[0], w45_0, be);
        be = fmaf(b3[1], w45_1, be);
        be = fmaf(b3[2], w45_2, be);
        be = fmaf(b2[0], w345_0, be);
        be = fmaf(b2[1], w345_1, be);
        be = fmaf(b2[2], w345_2, be);
        be = fmaf(b2[3], w345_3, be);
        be = fmaf(b1[0], w2345_0, be);
        be = fmaf(b1[1], w2345_1, be);
        be = fmaf(b1[2], w2345_2, be);
        be = fmaf(b1[3], w2345_3, be);
        be = fmaf(b1[4], w2345_4, be);
        s_weff[7] = be;
    }
    __syncthreads();

    const float w0 = s_weff[0], w1 = s_weff[1], w2 = s_weff[2], w3 = s_weff[3];
    const float w4 = s_weff[4], w5 = s_weff[5], w6 = s_weff[6], be = s_weff[7];

    const long long nquads = (long long)(nrows >> 2);
    const long long stride = (long long)gridDim.x * blockDim.x;

    for (long long i = (long long)blockIdx.x * blockDim.x + threadIdx.x;
         i < nquads; i += stride)
    {
        // 4 rows = 28 consecutive floats; base byte offset 112*i -> 16B aligned
        const float4* Xv = reinterpret_cast<const float4*>(X + i * 28);
        float4 p0 = __ldcs(Xv + 0);
        float4 p1 = __ldcs(Xv + 1);
        float4 p2 = __ldcs(Xv + 2);
        float4 p3 = __ldcs(Xv + 3);
        float4 p4 = __ldcs(Xv + 4);
        float4 p5 = __ldcs(Xv + 5);
        float4 p6 = __ldcs(Xv + 6);

        float f[28];
        f[0]=p0.x; f[1]=p0.y; f[2]=p0.z; f[3]=p0.w;
        f[4]=p1.x; f[5]=p1.y; f[6]=p1.z; f[7]=p1.w;
        f[8]=p2.x; f[9]=p2.y; f[10]=p2.z; f[11]=p2.w;
        f[12]=p3.x; f[13]=p3.y; f[14]=p3.z; f[15]=p3.w;
        f[16]=p4.x; f[17]=p4.y; f[18]=p4.z; f[19]=p4.w;
        f[20]=p5.x; f[21]=p5.y; f[22]=p5.z; f[23]=p5.w;
        f[24]=p6.x; f[25]=p6.y; f[26]=p6.z; f[27]=p6.w;

        float r[4];
        #pragma unroll
        for (int r4 = 0; r4 < 4; r4++) {
            const float* x = f + r4 * 7;
            float z = be;
            z = fmaf(x[0], w0, z);
            z = fmaf(x[1], w1, z);
            z = fmaf(x[2], w2, z);
            z = fmaf(x[3], w3, z);
            z = fmaf(x[4], w4, z);
            z = fmaf(x[5], w5, z);
            z = fmaf(x[6], w6, z);
            r[r4] = 1.0f / (1.0f + __expf(-z));
        }

        float4 o;
        o.x = r[0]; o.y = r[1]; o.z = r[2]; o.w = r[3];
        __stcs(reinterpret_cast<float4*>(out) + i, o);
    }

    // Tail rows (nrows % 4) — not hit for 4M rows, kept for safety.
    if (blockIdx.x == 0 && threadIdx.x == 0) {
        for (long long rr = (long long)(nrows & ~3); rr < nrows; rr++) {
            const float* x = X + rr * 7;
            float z = be;
            z = fmaf(x[0], w0, z);
            z = fmaf(x[1], w1, z);
            z = fmaf(x[2], w2, z);
            z = fmaf(x[3], w3, z);
            z = fmaf(x[4], w4, z);
            z = fmaf(x[5], w5, z);
            z = fmaf(x[6], w6, z);
            out[rr] = 1.0f / (1.0f + __expf(-z));
        }
    }
}

extern "C" void kernel_launch(void* const* d_in, const int* in_sizes, int n_in,
                              void* d_out, int out_size)
{
    const float* X  = (const float*)d_in[0];
    const float* W1 = (const float*)d_in[1];
    const float* b1 = (const float*)d_in[2];
    const float* W2 = (const float*)d_in[3];
    const float* b2 = (const float*)d_in[4];
    const float* W3 = (const float*)d_in[5];
    const float* b3 = (const float*)d_in[6];
    const float* W4 = (const float*)d_in[7];
    const float* b4 = (const float*)d_in[8];
    const float* W5 = (const float*)d_in[9];
    const float* b5 = (const float*)d_in[10];
    float* out = (float*)d_out;

    int nrows = in_sizes[0] / 7;

    int sms = 0;
    if (cudaDeviceGetAttribute(&sms, cudaDevAttrMultiProcessorCount, 0) != cudaSuccess || sms <= 0)
        sms = 148;
    int blocks = sms * 8;

    mlp_persistent_kernel<<<blocks, 256>>>(X, out, nrows,
                                           W1, b1, W2, b2, W3, b3, W4, b4, W5, b5);
}